// round 9
// baseline (speedup 1.0000x reference)
#include <cuda_runtime.h>
#include <cuda_bf16.h>
#include <cstdint>
#include <math.h>

// Dims fixed by the reference
#define BB 1024
#define KK 256
#define DD 1024
#define PP 768

typedef __nv_bfloat16 bf16;

// ---------------- scratch (device globals; no allocs allowed) ----------------
__device__ bf16  g_jh [BB * DD];   // joint (bf16)                [1024,1024]
__device__ bf16  g_ch [KK * DD];   // conf  (bf16)                [256,1024]
__device__ bf16  g_wqh[DD * PP];   // Wq (bf16, natural [D,P])    [1024,768]
__device__ bf16  g_wkh[DD * PP];   // Wk (bf16, natural [D,P])    [1024,768]
__device__ bf16  g_cp2[KK * DD];   // conf*prior (bf16, [K,D])    [256,1024]
__device__ bf16  g_qh [BB * PP];   // q (bf16)                    [1024,768]
__device__ bf16  g_kh [KK * PP];   // k (bf16)                    [256,768]
__device__ float g_s  [BB * KK];   // scores (fp32)               [1024,256]
__device__ bf16  g_ah [BB * KK];   // attn (bf16)                 [1024,256]

// ---------------- helpers ----------------------------------------------------
__device__ __forceinline__ uint32_t smem_u32(const void* p) {
    uint32_t a;
    asm("{ .reg .u64 t; cvta.to.shared.u64 t, %1; cvt.u32.u64 %0, t; }"
        : "=r"(a) : "l"(p));
    return a;
}

#define SWZ(off) ((off) ^ (((off) >> 3) & 0x70))

__device__ __forceinline__ void cp_async16(uint32_t dst, const void* src) {
    asm volatile("cp.async.cg.shared.global [%0], [%1], 16;"
                 :: "r"(dst), "l"(src));
}
#define CP_COMMIT() asm volatile("cp.async.commit_group;" ::: "memory")

__device__ __forceinline__ void ldm_x4(uint32_t* r, uint32_t addr) {
    asm volatile("ldmatrix.sync.aligned.m8n8.x4.shared.b16 {%0,%1,%2,%3}, [%4];"
                 : "=r"(r[0]), "=r"(r[1]), "=r"(r[2]), "=r"(r[3]) : "r"(addr));
}

__device__ __forceinline__ void ldm_x4_t(uint32_t* r, uint32_t addr) {
    asm volatile("ldmatrix.sync.aligned.m8n8.x4.trans.shared.b16 {%0,%1,%2,%3}, [%4];"
                 : "=r"(r[0]), "=r"(r[1]), "=r"(r[2]), "=r"(r[3]) : "r"(addr));
}

__device__ __forceinline__ void mma16816(float* c, const uint32_t* a,
                                         uint32_t b0, uint32_t b1) {
    asm volatile(
        "mma.sync.aligned.m16n8k16.row.col.f32.bf16.bf16.f32 "
        "{%0,%1,%2,%3}, {%4,%5,%6,%7}, {%8,%9}, {%0,%1,%2,%3};"
        : "+f"(c[0]), "+f"(c[1]), "+f"(c[2]), "+f"(c[3])
        : "r"(a[0]), "r"(a[1]), "r"(a[2]), "r"(a[3]), "r"(b0), "r"(b1));
}

// ---------------------------------------------------------------------------
// bf16 tensor-core GEMM:  C[M,N] = A[M,Ka] · B_op
//   BTRANS=1 (NT): B stored [N,Ka] K-major (row stride Ka)   -> plain ldmatrix
//   BTRANS=0 (NN): B stored [Ka,N] N-major (row stride ldb)  -> trans ldmatrix
// Block tile 64x64, 256 threads = 8 warps (2 over M x 4 over N),
// warp tile 32x16, K-chunk 64, cp.async double-buffered SW128 SMEM.
// EPI: 0 = store bf16   1 = store fp32 * alpha   2 = store fp32 + Cadd
// ---------------------------------------------------------------------------
#define EPI_BF16  0
#define EPI_SCALE 1
#define EPI_ADD   2
#define STAGE_BYTES 16384  // 8KB A + 8KB B

template <int EPI, int BTRANS>
__global__ __launch_bounds__(256) void gemm_mma(
    const bf16* __restrict__ A, const bf16* __restrict__ B,
    const float* __restrict__ Cadd, void* __restrict__ Cout,
    int Ka, int ldb, int Nout, int nchunk, float alpha)
{
    extern __shared__ char smem[];
    const uint32_t sb = smem_u32(smem);
    const int tid  = threadIdx.x;
    const int wid  = tid >> 5, lane = tid & 31;
    const int wm   = wid & 1;          // 2 warps over M: rows wm*32..+31
    const int wn   = wid >> 1;         // 4 warps over N: cols wn*16..+15
    const int row0 = blockIdx.y * 64, col0 = blockIdx.x * 64;

    const int g  = lane >> 3;          // ldmatrix lane group 0..3
    const int l8 = lane & 7;

    // A fragment (per m16 tile): rows wm*32 + (g&1)*8 + l8 (+mi*16), k byte-col (g>>1)*8
    const int a_row  = wm * 32 + (g & 1) * 8 + l8;
    const int a_koff = (g >> 1) * 8;
    // B fragment, NT form: rows = n (within [n][k] tile)
    const int bt_row  = wn * 16 + (g >> 1) * 8 + l8;
    const int bt_koff = (g & 1) * 8;
    // B fragment, NN form (trans ldmatrix on [k][n] tile):
    //   rows = k: (g&1)*8 + l8 (+k16*16), cols = wn*16 + (g>>1)*8
    const int bn_krow = (g & 1) * 8 + l8;
    const int bn_col  = wn * 16 + (g >> 1) * 8;

    float acc[2][2][4];
    #pragma unroll
    for (int mi = 0; mi < 2; mi++)
        #pragma unroll
        for (int ni = 0; ni < 2; ni++)
            #pragma unroll
            for (int j = 0; j < 4; j++) acc[mi][ni][j] = 0.f;

    auto load_chunk = [&](int c, int buf) {
        const uint32_t st = sb + buf * STAGE_BYTES;
        // A: 64 rows x 64 bf16 (K-major). 512 16B segs, 2 per thread.
        const bf16* gA = A + (size_t)row0 * Ka + c * 64;
        #pragma unroll
        for (int i = 0; i < 2; i++) {
            int s = tid + i * 256;
            int r = s >> 3, ks = s & 7;
            uint32_t off = SWZ((uint32_t)(r * 128 + ks * 16));
            cp_async16(st + off, gA + (size_t)r * Ka + ks * 8);
        }
        // B: 64x64 tile
        #pragma unroll
        for (int i = 0; i < 2; i++) {
            int s = tid + i * 256;
            int r = s >> 3, ks = s & 7;
            uint32_t off = SWZ((uint32_t)(r * 128 + ks * 16));
            const bf16* src = BTRANS
                ? B + (size_t)(col0 + r) * Ka + c * 64 + ks * 8       // [n][k]
                : B + (size_t)(c * 64 + r) * ldb + col0 + ks * 8;     // [k][n]
            cp_async16(st + 8192 + off, src);
        }
        CP_COMMIT();
    };

    load_chunk(0, 0);

    for (int c = 0; c < nchunk; c++) {
        const int buf = c & 1;
        if (c + 1 < nchunk) {
            load_chunk(c + 1, buf ^ 1);
            asm volatile("cp.async.wait_group 1;" ::: "memory");
        } else {
            asm volatile("cp.async.wait_group 0;" ::: "memory");
        }
        __syncthreads();

        const uint32_t stA = sb + buf * STAGE_BYTES;
        const uint32_t stB = stA + 8192;

        #pragma unroll
        for (int k16 = 0; k16 < 4; k16++) {
            const int kb = k16 * 16;  // bf16 units within the 64-chunk
            uint32_t a[2][4];
            #pragma unroll
            for (int mi = 0; mi < 2; mi++) {
                uint32_t off = SWZ((uint32_t)((a_row + mi * 16) * 128 +
                                              (kb + a_koff) * 2));
                ldm_x4(a[mi], stA + off);
            }
            uint32_t b[4];
            if (BTRANS) {
                uint32_t off = SWZ((uint32_t)(bt_row * 128 + (kb + bt_koff) * 2));
                ldm_x4(b, stB + off);
            } else {
                uint32_t off = SWZ((uint32_t)((kb + bn_krow) * 128 + bn_col * 2));
                ldm_x4_t(b, stB + off);
            }
            // regs: b0=(n0-7,k0-7) b1=(n0-7,k8-15) b2=(n8-15,k0-7) b3=(n8-15,k8-15)
            #pragma unroll
            for (int mi = 0; mi < 2; mi++)
                #pragma unroll
                for (int ni = 0; ni < 2; ni++)
                    mma16816(acc[mi][ni], a[mi], b[ni * 2], b[ni * 2 + 1]);
        }
        __syncthreads();
    }

    // ---- epilogue ----
    const int grp = lane >> 2, tig = lane & 3;
    const int rbase = row0 + wm * 32 + grp;
    const int cbase = col0 + wn * 16 + tig * 2;
    #pragma unroll
    for (int mi = 0; mi < 2; mi++) {
        #pragma unroll
        for (int ni = 0; ni < 2; ni++) {
            const int cc = cbase + ni * 8;
            const int r1 = rbase + mi * 16, r2 = r1 + 8;
            float* f = acc[mi][ni];
            if (EPI == EPI_BF16) {
                bf16* o = (bf16*)Cout;
                *(__nv_bfloat162*)&o[(size_t)r1 * Nout + cc] =
                    __floats2bfloat162_rn(f[0], f[1]);
                *(__nv_bfloat162*)&o[(size_t)r2 * Nout + cc] =
                    __floats2bfloat162_rn(f[2], f[3]);
            } else if (EPI == EPI_SCALE) {
                float* o = (float*)Cout;
                *(float2*)&o[(size_t)r1 * Nout + cc] =
                    make_float2(alpha * f[0], alpha * f[1]);
                *(float2*)&o[(size_t)r2 * Nout + cc] =
                    make_float2(alpha * f[2], alpha * f[3]);
            } else {
                float* o = (float*)Cout;
                float2 x = *(const float2*)&Cadd[(size_t)r1 * Nout + cc];
                float2 y = *(const float2*)&Cadd[(size_t)r2 * Nout + cc];
                *(float2*)&o[(size_t)r1 * Nout + cc] =
                    make_float2(f[0] + x.x, f[1] + x.y);
                *(float2*)&o[(size_t)r2 * Nout + cc] =
                    make_float2(f[2] + y.x, f[3] + y.y);
            }
        }
    }
}

// ---------------------------------------------------------------------------
// Single fused prep kernel: flat bf16 converts, no transposes.
//   range 0: joint  -> jh                          [1M elems]
//   range 1: conf   -> ch  AND  conf*prior -> cp2  [256K]
//   range 2: Wq     -> wqh                         [768K]
//   range 3: Wk     -> wkh                         [768K]
// 4 elems per thread.
// ---------------------------------------------------------------------------
#define N_JOINT (BB * DD)
#define N_CONF  (KK * DD)
#define N_W     (DD * PP)
#define PREP_TOTAL (N_JOINT + N_CONF + 2 * N_W)   // 2,883,584

__global__ void prep_all(const float* __restrict__ joint,
                         const float* __restrict__ conf,
                         const float* __restrict__ prior,
                         const float* __restrict__ Wq,
                         const float* __restrict__ Wk,
                         bf16* __restrict__ jh, bf16* __restrict__ ch,
                         bf16* __restrict__ cp2,
                         bf16* __restrict__ wqh, bf16* __restrict__ wkh)
{
    int i = (blockIdx.x * blockDim.x + threadIdx.x) * 4;
    if (i < N_JOINT) {
        float4 v = *(const float4*)&joint[i];
        *(__nv_bfloat162*)&jh[i]     = __floats2bfloat162_rn(v.x, v.y);
        *(__nv_bfloat162*)&jh[i + 2] = __floats2bfloat162_rn(v.z, v.w);
    } else if (i < N_JOINT + N_CONF) {
        int idx = i - N_JOINT;
        float4 v = *(const float4*)&conf[idx];
        *(__nv_bfloat162*)&ch[idx]     = __floats2bfloat162_rn(v.x, v.y);
        *(__nv_bfloat162*)&ch[idx + 2] = __floats2bfloat162_rn(v.z, v.w);
        float p = prior[idx >> 10];   // k = idx / DD (4-elem group never crosses rows)
        *(__nv_bfloat162*)&cp2[idx]     = __floats2bfloat162_rn(v.x * p, v.y * p);
        *(__nv_bfloat162*)&cp2[idx + 2] = __floats2bfloat162_rn(v.z * p, v.w * p);
    } else if (i < N_JOINT + N_CONF + N_W) {
        int idx = i - N_JOINT - N_CONF;
        float4 v = *(const float4*)&Wq[idx];
        *(__nv_bfloat162*)&wqh[idx]     = __floats2bfloat162_rn(v.x, v.y);
        *(__nv_bfloat162*)&wqh[idx + 2] = __floats2bfloat162_rn(v.z, v.w);
    } else {
        int idx = i - N_JOINT - N_CONF - N_W;
        float4 v = *(const float4*)&Wk[idx];
        *(__nv_bfloat162*)&wkh[idx]     = __floats2bfloat162_rn(v.x, v.y);
        *(__nv_bfloat162*)&wkh[idx + 2] = __floats2bfloat162_rn(v.z, v.w);
    }
}

// Row softmax over K=256 (fp32 in, bf16 out). One block per row.
__global__ __launch_bounds__(256) void softmax_rows(const float* __restrict__ s,
                                                    bf16* __restrict__ a)
{
    const int b = blockIdx.x;
    const int t = threadIdx.x;
    __shared__ float red[8];
    __shared__ float bcast;

    float v = s[(size_t)b * KK + t];

    float m = v;
    #pragma unroll
    for (int o = 16; o; o >>= 1) m = fmaxf(m, __shfl_xor_sync(~0u, m, o));
    if ((t & 31) == 0) red[t >> 5] = m;
    __syncthreads();
    if (t == 0) {
        float x = red[0];
        #pragma unroll
        for (int w = 1; w < 8; w++) x = fmaxf(x, red[w]);
        bcast = x;
    }
    __syncthreads();
    const float rowmax = bcast;

    float e = __expf(v - rowmax);

    float sm = e;
    #pragma unroll
    for (int o = 16; o; o >>= 1) sm += __shfl_xor_sync(~0u, sm, o);
    if ((t & 31) == 0) red[t >> 5] = sm;
    __syncthreads();
    if (t == 0) {
        float x = 0.f;
        #pragma unroll
        for (int w = 0; w < 8; w++) x += red[w];
        bcast = x;
    }
    __syncthreads();

    a[(size_t)b * KK + t] = __float2bfloat16(e / bcast);
}

// ---------------------------------------------------------------------------
extern "C" void kernel_launch(void* const* d_in, const int* in_sizes, int n_in,
                              void* d_out, int out_size)
{
    const float* joint = (const float*)d_in[0];   // [1024,1024]
    const float* conf  = (const float*)d_in[1];   // [256,1024]
    const float* prior = (const float*)d_in[2];   // [256,1]
    const float* Wq    = (const float*)d_in[3];   // [1024,768]
    const float* Wk    = (const float*)d_in[4];   // [1024,768]
    float* out = (float*)d_out;                   // [1024,1024]

    bf16 *jh, *ch, *wqh, *wkh, *cp2, *qh, *kh, *ah; float* s;
    cudaGetSymbolAddress((void**)&jh,  g_jh);
    cudaGetSymbolAddress((void**)&ch,  g_ch);
    cudaGetSymbolAddress((void**)&wqh, g_wqh);
    cudaGetSymbolAddress((void**)&wkh, g_wkh);
    cudaGetSymbolAddress((void**)&cp2, g_cp2);
    cudaGetSymbolAddress((void**)&qh,  g_qh);
    cudaGetSymbolAddress((void**)&kh,  g_kh);
    cudaGetSymbolAddress((void**)&s,   g_s);
    cudaGetSymbolAddress((void**)&ah,  g_ah);

    const int SMEM = 2 * STAGE_BYTES;  // 32 KB

    // --- prep: single fused bf16 convert (no transposes) ---
    prep_all<<<PREP_TOTAL / 1024, 256>>>(joint, conf, prior, Wq, Wk,
                                         jh, ch, cp2, wqh, wkh);

    // --- q = joint @ Wq          NN, grid 12x16 = 192 CTAs ---
    gemm_mma<EPI_BF16, 0><<<dim3(PP / 64, BB / 64), 256, SMEM>>>(
        jh, wqh, nullptr, qh, DD, PP, PP, DD / 64, 1.f);
    // --- k = conf @ Wk           NN, grid 12x4 = 48 CTAs ---
    gemm_mma<EPI_BF16, 0><<<dim3(PP / 64, KK / 64), 256, SMEM>>>(
        ch, wkh, nullptr, kh, DD, PP, PP, DD / 64, 1.f);
    // --- scores = (q @ k^T)/32   NT, grid 4x16 = 64 CTAs ---
    gemm_mma<EPI_SCALE, 1><<<dim3(KK / 64, BB / 64), 256, SMEM>>>(
        qh, kh, nullptr, s, PP, PP, KK, PP / 64, 1.f / 32.f);
    // --- softmax rows (fp32 -> bf16 attn) ---
    softmax_rows<<<BB, 256>>>(s, ah);
    // --- out = attn @ (conf*prior) + joint   NN, grid 16x16 = 256 CTAs ---
    gemm_mma<EPI_ADD, 0><<<dim3(DD / 64, BB / 64), 256, SMEM>>>(
        ah, cp2, joint, out, KK, DD, DD, KK / 64, 1.f);
}

// round 10
// speedup vs baseline: 1.4540x; 1.4540x over previous
#include <cuda_runtime.h>
#include <cuda_bf16.h>
#include <cstdint>
#include <math.h>

// Dims fixed by the reference
#define BB 1024
#define KK 256
#define DD 1024
#define PP 768

typedef __nv_bfloat16 bf16;

// ---------------- scratch (device globals; no allocs allowed) ----------------
__device__ bf16  g_jh [BB * DD];       // joint (bf16)              [1024,1024]
__device__ bf16  g_ch [KK * DD];       // conf  (bf16)              [256,1024]
__device__ bf16  g_wqh[DD * PP];       // Wq (bf16, natural [D,P])  [1024,768]
__device__ bf16  g_wkh[DD * PP];       // Wk (bf16, natural [D,P])  [1024,768]
__device__ bf16  g_cp2[KK * DD];       // conf*prior (bf16, [K,D])  [256,1024]
__device__ bf16  g_qh [BB * PP];       // q (bf16)                  [1024,768]
__device__ bf16  g_kh [KK * PP];       // k (bf16)                  [256,768]
__device__ float g_s  [4 * BB * KK];   // score partials (fp32) x4  [4,1024,256]
__device__ bf16  g_ah [BB * KK];       // attn (bf16)               [1024,256]

// ---------------- helpers ----------------------------------------------------
__device__ __forceinline__ uint32_t smem_u32(const void* p) {
    uint32_t a;
    asm("{ .reg .u64 t; cvta.to.shared.u64 t, %1; cvt.u32.u64 %0, t; }"
        : "=r"(a) : "l"(p));
    return a;
}

#define SWZ(off) ((off) ^ (((off) >> 3) & 0x70))

__device__ __forceinline__ void cp_async16(uint32_t dst, const void* src) {
    asm volatile("cp.async.cg.shared.global [%0], [%1], 16;"
                 :: "r"(dst), "l"(src));
}
#define CP_COMMIT() asm volatile("cp.async.commit_group;" ::: "memory")

__device__ __forceinline__ void ldm_x4(uint32_t* r, uint32_t addr) {
    asm volatile("ldmatrix.sync.aligned.m8n8.x4.shared.b16 {%0,%1,%2,%3}, [%4];"
                 : "=r"(r[0]), "=r"(r[1]), "=r"(r[2]), "=r"(r[3]) : "r"(addr));
}

__device__ __forceinline__ void ldm_x4_t(uint32_t* r, uint32_t addr) {
    asm volatile("ldmatrix.sync.aligned.m8n8.x4.trans.shared.b16 {%0,%1,%2,%3}, [%4];"
                 : "=r"(r[0]), "=r"(r[1]), "=r"(r[2]), "=r"(r[3]) : "r"(addr));
}

__device__ __forceinline__ void mma16816(float* c, const uint32_t* a,
                                         uint32_t b0, uint32_t b1) {
    asm volatile(
        "mma.sync.aligned.m16n8k16.row.col.f32.bf16.bf16.f32 "
        "{%0,%1,%2,%3}, {%4,%5,%6,%7}, {%8,%9}, {%0,%1,%2,%3};"
        : "+f"(c[0]), "+f"(c[1]), "+f"(c[2]), "+f"(c[3])
        : "r"(a[0]), "r"(a[1]), "r"(a[2]), "r"(a[3]), "r"(b0), "r"(b1));
}

// ---------------------------------------------------------------------------
// Core bf16 tensor-core GEMM tile:  C[64x64 @ (row0,col0)] = A[M,Ka] · B_op
//   BTRANS=1 (NT): B stored [N,Ka] K-major       -> plain ldmatrix
//   BTRANS=0 (NN): B stored [Ka,N] N-major (ldb) -> trans ldmatrix
// 128 threads = 4 warps (2 over M x 2 over N), warp tile 32x32.
// K-chunk 64, cp.async double-buffered SW128 SMEM, register double-buffered
// fragments (prefetch next k16 during current MMAs).
// koff: starting k offset (elements) — used for split-K.
// EPI: 0 = store bf16   1 = store fp32 * alpha   2 = store fp32 + Cadd
// ---------------------------------------------------------------------------
#define EPI_BF16  0
#define EPI_SCALE 1
#define EPI_ADD   2
#define STAGE_BYTES 16384  // 8KB A + 8KB B

template <int EPI, int BTRANS>
__device__ __forceinline__ void gemm_core(
    const bf16* __restrict__ A, const bf16* __restrict__ B,
    const float* __restrict__ Cadd, void* __restrict__ Cout,
    int row0, int col0, int Ka, int ldb, int Nout, int nchunk, int koff,
    float alpha)
{
    extern __shared__ char smem[];
    const uint32_t sb = smem_u32(smem);
    const int tid  = threadIdx.x;
    const int wid  = tid >> 5, lane = tid & 31;
    const int wm   = wid & 1;          // 2 warps over M: rows wm*32..+31
    const int wn   = wid >> 1;         // 2 warps over N: cols wn*32..+31

    const int g  = lane >> 3;          // ldmatrix lane group 0..3
    const int l8 = lane & 7;

    // A fragment (per m16 tile mi)
    const int a_row  = wm * 32 + (g & 1) * 8 + l8;   // + mi*16
    const int a_koff = (g >> 1) * 8;
    // B fragment NT (per n16 group pi)
    const int bt_row  = wn * 32 + (g >> 1) * 8 + l8; // + pi*16
    const int bt_koff = (g & 1) * 8;
    // B fragment NN (trans ldmatrix on [k][n] tile, per n16 group pi)
    const int bn_krow = (g & 1) * 8 + l8;            // + kb
    const int bn_col  = wn * 32 + (g >> 1) * 8;      // + pi*16

    float acc[2][4][4];
    #pragma unroll
    for (int mi = 0; mi < 2; mi++)
        #pragma unroll
        for (int ni = 0; ni < 4; ni++)
            #pragma unroll
            for (int j = 0; j < 4; j++) acc[mi][ni][j] = 0.f;

    auto load_chunk = [&](int c, int buf) {
        const uint32_t st = sb + buf * STAGE_BYTES;
        const bf16* gA = A + (size_t)row0 * Ka + koff + c * 64;
        #pragma unroll
        for (int i = 0; i < 4; i++) {
            int s = tid + i * 128;
            int r = s >> 3, ks = s & 7;
            uint32_t off = SWZ((uint32_t)(r * 128 + ks * 16));
            cp_async16(st + off, gA + (size_t)r * Ka + ks * 8);
        }
        #pragma unroll
        for (int i = 0; i < 4; i++) {
            int s = tid + i * 128;
            int r = s >> 3, ks = s & 7;
            uint32_t off = SWZ((uint32_t)(r * 128 + ks * 16));
            const bf16* src = BTRANS
                ? B + (size_t)(col0 + r) * Ka + koff + c * 64 + ks * 8
                : B + (size_t)(koff + c * 64 + r) * ldb + col0 + ks * 8;
            cp_async16(st + 8192 + off, src);
        }
        CP_COMMIT();
    };

    auto load_frags = [&](uint32_t stA, uint32_t stB, int kb,
                          uint32_t (*fa)[4], uint32_t (*fb)[4]) {
        #pragma unroll
        for (int mi = 0; mi < 2; mi++)
            ldm_x4(fa[mi], stA + SWZ((uint32_t)((a_row + mi * 16) * 128 +
                                                (kb + a_koff) * 2)));
        #pragma unroll
        for (int pi = 0; pi < 2; pi++) {
            if (BTRANS)
                ldm_x4(fb[pi], stB + SWZ((uint32_t)((bt_row + pi * 16) * 128 +
                                                    (kb + bt_koff) * 2)));
            else
                ldm_x4_t(fb[pi], stB + SWZ((uint32_t)((kb + bn_krow) * 128 +
                                                      (bn_col + pi * 16) * 2)));
        }
    };

    load_chunk(0, 0);

    for (int c = 0; c < nchunk; c++) {
        const int buf = c & 1;
        if (c + 1 < nchunk) {
            load_chunk(c + 1, buf ^ 1);
            asm volatile("cp.async.wait_group 1;" ::: "memory");
        } else {
            asm volatile("cp.async.wait_group 0;" ::: "memory");
        }
        __syncthreads();

        const uint32_t stA = sb + buf * STAGE_BYTES;
        const uint32_t stB = stA + 8192;

        // register double-buffered fragment pipeline over 4 k16-steps
        uint32_t fa[2][2][4], fb[2][2][4];
        load_frags(stA, stB, 0, fa[0], fb[0]);
        #pragma unroll
        for (int k16 = 0; k16 < 4; k16++) {
            const int cur = k16 & 1, nxt = cur ^ 1;
            if (k16 < 3)
                load_frags(stA, stB, (k16 + 1) * 16, fa[nxt], fb[nxt]);
            // b regs per pi: b0=(n0-7,k0-7) b1=(n0-7,k8-15) b2=(n8-15,k0-7) b3=(n8-15,k8-15)
            #pragma unroll
            for (int mi = 0; mi < 2; mi++)
                #pragma unroll
                for (int ni = 0; ni < 4; ni++)
                    mma16816(acc[mi][ni], fa[cur][mi],
                             fb[cur][ni >> 1][(ni & 1) * 2],
                             fb[cur][ni >> 1][(ni & 1) * 2 + 1]);
        }
        __syncthreads();
    }

    // ---- epilogue ----
    const int grp = lane >> 2, tig = lane & 3;
    const int rbase = row0 + wm * 32 + grp;
    const int cbase = col0 + wn * 32 + tig * 2;
    #pragma unroll
    for (int mi = 0; mi < 2; mi++) {
        #pragma unroll
        for (int ni = 0; ni < 4; ni++) {
            const int cc = cbase + ni * 8;
            const int r1 = rbase + mi * 16, r2 = r1 + 8;
            float* f = acc[mi][ni];
            if (EPI == EPI_BF16) {
                bf16* o = (bf16*)Cout;
                *(__nv_bfloat162*)&o[(size_t)r1 * Nout + cc] =
                    __floats2bfloat162_rn(f[0], f[1]);
                *(__nv_bfloat162*)&o[(size_t)r2 * Nout + cc] =
                    __floats2bfloat162_rn(f[2], f[3]);
            } else if (EPI == EPI_SCALE) {
                float* o = (float*)Cout;
                *(float2*)&o[(size_t)r1 * Nout + cc] =
                    make_float2(alpha * f[0], alpha * f[1]);
                *(float2*)&o[(size_t)r2 * Nout + cc] =
                    make_float2(alpha * f[2], alpha * f[3]);
            } else {
                float* o = (float*)Cout;
                float2 x = *(const float2*)&Cadd[(size_t)r1 * Nout + cc];
                float2 y = *(const float2*)&Cadd[(size_t)r2 * Nout + cc];
                *(float2*)&o[(size_t)r1 * Nout + cc] =
                    make_float2(f[0] + x.x, f[1] + x.y);
                *(float2*)&o[(size_t)r2 * Nout + cc] =
                    make_float2(f[2] + y.x, f[3] + y.y);
            }
        }
    }
}

// ---------------------------------------------------------------------------
// GEMM wrappers
// ---------------------------------------------------------------------------
// q-proj (192 tiles) and k-proj (48 tiles) fused in one launch. NN.
__global__ __launch_bounds__(128) void proj_kernel(
    const bf16* __restrict__ jh, const bf16* __restrict__ wqh,
    const bf16* __restrict__ ch, const bf16* __restrict__ wkh,
    bf16* __restrict__ qh, bf16* __restrict__ kh)
{
    const int bx = blockIdx.x;
    if (bx < 192) {   // q: 16 (M) x 12 (N)
        gemm_core<EPI_BF16, 0>(jh, wqh, nullptr, qh,
                               (bx / 12) * 64, (bx % 12) * 64,
                               DD, PP, PP, DD / 64, 0, 1.f);
    } else {          // k: 4 (M) x 12 (N)
        const int b2 = bx - 192;
        gemm_core<EPI_BF16, 0>(ch, wkh, nullptr, kh,
                               (b2 / 12) * 64, (b2 % 12) * 64,
                               DD, PP, PP, DD / 64, 0, 1.f);
    }
}

// scores split-K x4: z in 0..3 handles K chunks [z*3, z*3+3). NT.
__global__ __launch_bounds__(128) void scores_kernel(
    const bf16* __restrict__ qh, const bf16* __restrict__ kh,
    float* __restrict__ s)
{
    const int z = blockIdx.z;
    gemm_core<EPI_SCALE, 1>(qh, kh, nullptr, s + (size_t)z * BB * KK,
                            blockIdx.y * 64, blockIdx.x * 64,
                            PP, PP, KK, 3, z * 192, 1.f / 32.f);
}

// out = attn @ (conf*prior) + joint. NN.
__global__ __launch_bounds__(128) void out_kernel(
    const bf16* __restrict__ ah, const bf16* __restrict__ cp2,
    const float* __restrict__ joint, float* __restrict__ out)
{
    gemm_core<EPI_ADD, 0>(ah, cp2, joint, out,
                          blockIdx.y * 64, blockIdx.x * 64,
                          KK, DD, DD, KK / 64, 0, 1.f);
}

// ---------------------------------------------------------------------------
// Single fused prep kernel: flat bf16 converts, no transposes.
// ---------------------------------------------------------------------------
#define N_JOINT (BB * DD)
#define N_CONF  (KK * DD)
#define N_W     (DD * PP)
#define PREP_TOTAL (N_JOINT + N_CONF + 2 * N_W)

__global__ void prep_all(const float* __restrict__ joint,
                         const float* __restrict__ conf,
                         const float* __restrict__ prior,
                         const float* __restrict__ Wq,
                         const float* __restrict__ Wk,
                         bf16* __restrict__ jh, bf16* __restrict__ ch,
                         bf16* __restrict__ cp2,
                         bf16* __restrict__ wqh, bf16* __restrict__ wkh)
{
    int i = (blockIdx.x * blockDim.x + threadIdx.x) * 4;
    if (i < N_JOINT) {
        float4 v = *(const float4*)&joint[i];
        *(__nv_bfloat162*)&jh[i]     = __floats2bfloat162_rn(v.x, v.y);
        *(__nv_bfloat162*)&jh[i + 2] = __floats2bfloat162_rn(v.z, v.w);
    } else if (i < N_JOINT + N_CONF) {
        int idx = i - N_JOINT;
        float4 v = *(const float4*)&conf[idx];
        *(__nv_bfloat162*)&ch[idx]     = __floats2bfloat162_rn(v.x, v.y);
        *(__nv_bfloat162*)&ch[idx + 2] = __floats2bfloat162_rn(v.z, v.w);
        float p = prior[idx >> 10];   // k = idx / DD (4-group never crosses rows)
        *(__nv_bfloat162*)&cp2[idx]     = __floats2bfloat162_rn(v.x * p, v.y * p);
        *(__nv_bfloat162*)&cp2[idx + 2] = __floats2bfloat162_rn(v.z * p, v.w * p);
    } else if (i < N_JOINT + N_CONF + N_W) {
        int idx = i - N_JOINT - N_CONF;
        float4 v = *(const float4*)&Wq[idx];
        *(__nv_bfloat162*)&wqh[idx]     = __floats2bfloat162_rn(v.x, v.y);
        *(__nv_bfloat162*)&wqh[idx + 2] = __floats2bfloat162_rn(v.z, v.w);
    } else {
        int idx = i - N_JOINT - N_CONF - N_W;
        float4 v = *(const float4*)&Wk[idx];
        *(__nv_bfloat162*)&wkh[idx]     = __floats2bfloat162_rn(v.x, v.y);
        *(__nv_bfloat162*)&wkh[idx + 2] = __floats2bfloat162_rn(v.z, v.w);
    }
}

// Row softmax over K=256, summing 4 split-K partials. fp32 in, bf16 out.
__global__ __launch_bounds__(256) void softmax4(const float* __restrict__ s,
                                                bf16* __restrict__ a)
{
    const int b = blockIdx.x;
    const int t = threadIdx.x;
    __shared__ float red[8];
    __shared__ float bcast;

    const size_t off = (size_t)b * KK + t;
    float v = s[off] + s[off + (size_t)BB * KK]
            + s[off + 2 * (size_t)BB * KK] + s[off + 3 * (size_t)BB * KK];

    float m = v;
    #pragma unroll
    for (int o = 16; o; o >>= 1) m = fmaxf(m, __shfl_xor_sync(~0u, m, o));
    if ((t & 31) == 0) red[t >> 5] = m;
    __syncthreads();
    if (t == 0) {
        float x = red[0];
        #pragma unroll
        for (int w = 1; w < 8; w++) x = fmaxf(x, red[w]);
        bcast = x;
    }
    __syncthreads();
    const float rowmax = bcast;

    float e = __expf(v - rowmax);

    float sm = e;
    #pragma unroll
    for (int o = 16; o; o >>= 1) sm += __shfl_xor_sync(~0u, sm, o);
    if ((t & 31) == 0) red[t >> 5] = sm;
    __syncthreads();
    if (t == 0) {
        float x = 0.f;
        #pragma unroll
        for (int w = 0; w < 8; w++) x += red[w];
        bcast = x;
    }
    __syncthreads();

    a[off] = __float2bfloat16(e / bcast);
}

// ---------------------------------------------------------------------------
extern "C" void kernel_launch(void* const* d_in, const int* in_sizes, int n_in,
                              void* d_out, int out_size)
{
    const float* joint = (const float*)d_in[0];   // [1024,1024]
    const float* conf  = (const float*)d_in[1];   // [256,1024]
    const float* prior = (const float*)d_in[2];   // [256,1]
    const float* Wq    = (const float*)d_in[3];   // [1024,768]
    const float* Wk    = (const float*)d_in[4];   // [1024,768]
    float* out = (float*)d_out;                   // [1024,1024]

    bf16 *jh, *ch, *wqh, *wkh, *cp2, *qh, *kh, *ah; float* s;
    cudaGetSymbolAddress((void**)&jh,  g_jh);
    cudaGetSymbolAddress((void**)&ch,  g_ch);
    cudaGetSymbolAddress((void**)&wqh, g_wqh);
    cudaGetSymbolAddress((void**)&wkh, g_wkh);
    cudaGetSymbolAddress((void**)&cp2, g_cp2);
    cudaGetSymbolAddress((void**)&qh,  g_qh);
    cudaGetSymbolAddress((void**)&kh,  g_kh);
    cudaGetSymbolAddress((void**)&s,   g_s);
    cudaGetSymbolAddress((void**)&ah,  g_ah);

    const int SMEM = 2 * STAGE_BYTES;  // 32 KB (<48KB default dyn limit)

    // 1) prep: single fused bf16 convert
    prep_all<<<PREP_TOTAL / 1024, 256>>>(joint, conf, prior, Wq, Wk,
                                         jh, ch, cp2, wqh, wkh);
    // 2) q-proj + k-proj fused: 240 CTAs
    proj_kernel<<<240, 128, SMEM>>>(jh, wqh, ch, wkh, qh, kh);
    // 3) scores split-K x4: 4x16x4 = 256 CTAs, fp32 partials
    scores_kernel<<<dim3(KK / 64, BB / 64, 4), 128, SMEM>>>(qh, kh, s);
    // 4) softmax over summed partials -> bf16 attn
    softmax4<<<BB, 256>>>(s, ah);
    // 5) out = attn @ (conf*prior) + joint: 16x16 = 256 CTAs
    out_kernel<<<dim3(DD / 64, BB / 64), 128, SMEM>>>(ah, cp2, joint, out);
}

// round 11
// speedup vs baseline: 1.5747x; 1.0830x over previous
#include <cuda_runtime.h>
#include <cuda_bf16.h>
#include <cstdint>
#include <math.h>

// Dims fixed by the reference
#define BB 1024
#define KK 256
#define DD 1024
#define PP 768

typedef __nv_bfloat16 bf16;

// ---------------- scratch (device globals; no allocs allowed) ----------------
__device__ bf16  g_jh [BB * DD];       // joint (bf16)              [1024,1024]
__device__ bf16  g_ch [KK * DD];       // conf  (bf16)              [256,1024]
__device__ bf16  g_wqh[DD * PP];       // Wq (bf16, natural [D,P])  [1024,768]
__device__ bf16  g_wkh[DD * PP];       // Wk (bf16, natural [D,P])  [1024,768]
__device__ bf16  g_cp2[KK * DD];       // conf*prior (bf16, [K,D])  [256,1024]
__device__ bf16  g_qh [BB * PP];       // q (bf16)                  [1024,768]
__device__ bf16  g_kh [KK * PP];       // k (bf16)                  [256,768]
__device__ float g_s  [4 * BB * KK];   // score partials (fp32) x4  [4,1024,256]
__device__ bf16  g_ah [BB * KK];       // attn (bf16)               [1024,256]

// ---------------- helpers ----------------------------------------------------
__device__ __forceinline__ uint32_t smem_u32(const void* p) {
    uint32_t a;
    asm("{ .reg .u64 t; cvta.to.shared.u64 t, %1; cvt.u32.u64 %0, t; }"
        : "=r"(a) : "l"(p));
    return a;
}

#define SWZ(off) ((off) ^ (((off) >> 3) & 0x70))

__device__ __forceinline__ void cp_async16(uint32_t dst, const void* src) {
    asm volatile("cp.async.cg.shared.global [%0], [%1], 16;"
                 :: "r"(dst), "l"(src));
}
#define CP_COMMIT() asm volatile("cp.async.commit_group;" ::: "memory")

__device__ __forceinline__ void ldm_x4(uint32_t* r, uint32_t addr) {
    asm volatile("ldmatrix.sync.aligned.m8n8.x4.shared.b16 {%0,%1,%2,%3}, [%4];"
                 : "=r"(r[0]), "=r"(r[1]), "=r"(r[2]), "=r"(r[3]) : "r"(addr));
}

__device__ __forceinline__ void ldm_x4_t(uint32_t* r, uint32_t addr) {
    asm volatile("ldmatrix.sync.aligned.m8n8.x4.trans.shared.b16 {%0,%1,%2,%3}, [%4];"
                 : "=r"(r[0]), "=r"(r[1]), "=r"(r[2]), "=r"(r[3]) : "r"(addr));
}

__device__ __forceinline__ void mma16816(float* c, const uint32_t* a,
                                         uint32_t b0, uint32_t b1) {
    asm volatile(
        "mma.sync.aligned.m16n8k16.row.col.f32.bf16.bf16.f32 "
        "{%0,%1,%2,%3}, {%4,%5,%6,%7}, {%8,%9}, {%0,%1,%2,%3};"
        : "+f"(c[0]), "+f"(c[1]), "+f"(c[2]), "+f"(c[3])
        : "r"(a[0]), "r"(a[1]), "r"(a[2]), "r"(a[3]), "r"(b0), "r"(b1));
}

// ---------------------------------------------------------------------------
// Core bf16 tensor-core GEMM tile:  C[64x64 @ (row0,col0)] = A[M,Ka] · B_op
//   BTRANS=1 (NT): B stored [N,Ka] K-major       -> plain ldmatrix
//   BTRANS=0 (NN): B stored [Ka,N] N-major (ldb) -> trans ldmatrix
// 128 threads = 4 warps (2 over M x 2 over N), warp tile 32x32.
// K-chunk 64, cp.async double-buffered SW128 SMEM, register double-buffered
// fragments (prefetch next k16 during current MMAs).
// koff: starting k offset (elements) — used for split-K.
// EPI: 0 = store bf16   1 = store fp32 * alpha   2 = store fp32 + Cadd
// ---------------------------------------------------------------------------
#define EPI_BF16  0
#define EPI_SCALE 1
#define EPI_ADD   2
#define STAGE_BYTES 16384  // 8KB A + 8KB B

template <int EPI, int BTRANS>
__device__ __forceinline__ void gemm_core(
    const bf16* __restrict__ A, const bf16* __restrict__ B,
    const float* __restrict__ Cadd, void* __restrict__ Cout,
    int row0, int col0, int Ka, int ldb, int Nout, int nchunk, int koff,
    float alpha)
{
    extern __shared__ char smem[];
    const uint32_t sb = smem_u32(smem);
    const int tid  = threadIdx.x;
    const int wid  = tid >> 5, lane = tid & 31;
    const int wm   = wid & 1;          // 2 warps over M: rows wm*32..+31
    const int wn   = wid >> 1;         // 2 warps over N: cols wn*32..+31

    const int g  = lane >> 3;          // ldmatrix lane group 0..3
    const int l8 = lane & 7;

    // A fragment (per m16 tile mi)
    const int a_row  = wm * 32 + (g & 1) * 8 + l8;   // + mi*16
    const int a_koff = (g >> 1) * 8;
    // B fragment NT (per n16 group pi)
    const int bt_row  = wn * 32 + (g >> 1) * 8 + l8; // + pi*16
    const int bt_koff = (g & 1) * 8;
    // B fragment NN (trans ldmatrix on [k][n] tile, per n16 group pi)
    const int bn_krow = (g & 1) * 8 + l8;            // + kb
    const int bn_col  = wn * 32 + (g >> 1) * 8;      // + pi*16

    float acc[2][4][4];
    #pragma unroll
    for (int mi = 0; mi < 2; mi++)
        #pragma unroll
        for (int ni = 0; ni < 4; ni++)
            #pragma unroll
            for (int j = 0; j < 4; j++) acc[mi][ni][j] = 0.f;

    auto load_chunk = [&](int c, int buf) {
        const uint32_t st = sb + buf * STAGE_BYTES;
        const bf16* gA = A + (size_t)row0 * Ka + koff + c * 64;
        #pragma unroll
        for (int i = 0; i < 4; i++) {
            int s = tid + i * 128;
            int r = s >> 3, ks = s & 7;
            uint32_t off = SWZ((uint32_t)(r * 128 + ks * 16));
            cp_async16(st + off, gA + (size_t)r * Ka + ks * 8);
        }
        #pragma unroll
        for (int i = 0; i < 4; i++) {
            int s = tid + i * 128;
            int r = s >> 3, ks = s & 7;
            uint32_t off = SWZ((uint32_t)(r * 128 + ks * 16));
            const bf16* src = BTRANS
                ? B + (size_t)(col0 + r) * Ka + koff + c * 64 + ks * 8
                : B + (size_t)(koff + c * 64 + r) * ldb + col0 + ks * 8;
            cp_async16(st + 8192 + off, src);
        }
        CP_COMMIT();
    };

    auto load_frags = [&](uint32_t stA, uint32_t stB, int kb,
                          uint32_t (*fa)[4], uint32_t (*fb)[4]) {
        #pragma unroll
        for (int mi = 0; mi < 2; mi++)
            ldm_x4(fa[mi], stA + SWZ((uint32_t)((a_row + mi * 16) * 128 +
                                                (kb + a_koff) * 2)));
        #pragma unroll
        for (int pi = 0; pi < 2; pi++) {
            if (BTRANS)
                ldm_x4(fb[pi], stB + SWZ((uint32_t)((bt_row + pi * 16) * 128 +
                                                    (kb + bt_koff) * 2)));
            else
                ldm_x4_t(fb[pi], stB + SWZ((uint32_t)((kb + bn_krow) * 128 +
                                                      (bn_col + pi * 16) * 2)));
        }
    };

    load_chunk(0, 0);

    for (int c = 0; c < nchunk; c++) {
        const int buf = c & 1;
        if (c + 1 < nchunk) {
            load_chunk(c + 1, buf ^ 1);
            asm volatile("cp.async.wait_group 1;" ::: "memory");
        } else {
            asm volatile("cp.async.wait_group 0;" ::: "memory");
        }
        __syncthreads();

        const uint32_t stA = sb + buf * STAGE_BYTES;
        const uint32_t stB = stA + 8192;

        // register double-buffered fragment pipeline over 4 k16-steps
        uint32_t fa[2][2][4], fb[2][2][4];
        load_frags(stA, stB, 0, fa[0], fb[0]);
        #pragma unroll
        for (int k16 = 0; k16 < 4; k16++) {
            const int cur = k16 & 1, nxt = cur ^ 1;
            if (k16 < 3)
                load_frags(stA, stB, (k16 + 1) * 16, fa[nxt], fb[nxt]);
            // b regs per pi: b0=(n0-7,k0-7) b1=(n0-7,k8-15) b2=(n8-15,k0-7) b3=(n8-15,k8-15)
            #pragma unroll
            for (int mi = 0; mi < 2; mi++)
                #pragma unroll
                for (int ni = 0; ni < 4; ni++)
                    mma16816(acc[mi][ni], fa[cur][mi],
                             fb[cur][ni >> 1][(ni & 1) * 2],
                             fb[cur][ni >> 1][(ni & 1) * 2 + 1]);
        }
        __syncthreads();
    }

    // ---- epilogue ----
    const int grp = lane >> 2, tig = lane & 3;
    const int rbase = row0 + wm * 32 + grp;
    const int cbase = col0 + wn * 32 + tig * 2;
    #pragma unroll
    for (int mi = 0; mi < 2; mi++) {
        #pragma unroll
        for (int ni = 0; ni < 4; ni++) {
            const int cc = cbase + ni * 8;
            const int r1 = rbase + mi * 16, r2 = r1 + 8;
            float* f = acc[mi][ni];
            if (EPI == EPI_BF16) {
                bf16* o = (bf16*)Cout;
                *(__nv_bfloat162*)&o[(size_t)r1 * Nout + cc] =
                    __floats2bfloat162_rn(f[0], f[1]);
                *(__nv_bfloat162*)&o[(size_t)r2 * Nout + cc] =
                    __floats2bfloat162_rn(f[2], f[3]);
            } else if (EPI == EPI_SCALE) {
                float* o = (float*)Cout;
                *(float2*)&o[(size_t)r1 * Nout + cc] =
                    make_float2(alpha * f[0], alpha * f[1]);
                *(float2*)&o[(size_t)r2 * Nout + cc] =
                    make_float2(alpha * f[2], alpha * f[3]);
            } else {
                float* o = (float*)Cout;
                float2 x = *(const float2*)&Cadd[(size_t)r1 * Nout + cc];
                float2 y = *(const float2*)&Cadd[(size_t)r2 * Nout + cc];
                *(float2*)&o[(size_t)r1 * Nout + cc] =
                    make_float2(f[0] + x.x, f[1] + x.y);
                *(float2*)&o[(size_t)r2 * Nout + cc] =
                    make_float2(f[2] + y.x, f[3] + y.y);
            }
        }
    }
}

// ---------------------------------------------------------------------------
// GEMM wrappers
// ---------------------------------------------------------------------------
// q-proj (192 tiles) and k-proj (48 tiles) fused in one launch. NN.
__global__ __launch_bounds__(128) void proj_kernel(
    const bf16* __restrict__ jh, const bf16* __restrict__ wqh,
    const bf16* __restrict__ ch, const bf16* __restrict__ wkh,
    bf16* __restrict__ qh, bf16* __restrict__ kh)
{
    const int bx = blockIdx.x;
    if (bx < 192) {   // q: 16 (M) x 12 (N)
        gemm_core<EPI_BF16, 0>(jh, wqh, nullptr, qh,
                               (bx / 12) * 64, (bx % 12) * 64,
                               DD, PP, PP, DD / 64, 0, 1.f);
    } else {          // k: 4 (M) x 12 (N)
        const int b2 = bx - 192;
        gemm_core<EPI_BF16, 0>(ch, wkh, nullptr, kh,
                               (b2 / 12) * 64, (b2 % 12) * 64,
                               DD, PP, PP, DD / 64, 0, 1.f);
    }
}

// scores split-K x4: z in 0..3 handles K chunks [z*3, z*3+3). NT.
__global__ __launch_bounds__(128) void scores_kernel(
    const bf16* __restrict__ qh, const bf16* __restrict__ kh,
    float* __restrict__ s)
{
    const int z = blockIdx.z;
    gemm_core<EPI_SCALE, 1>(qh, kh, nullptr, s + (size_t)z * BB * KK,
                            blockIdx.y * 64, blockIdx.x * 64,
                            PP, PP, KK, 3, z * 192, 1.f / 32.f);
}

// out = attn @ (conf*prior) + joint. NN.
__global__ __launch_bounds__(128) void out_kernel(
    const bf16* __restrict__ ah, const bf16* __restrict__ cp2,
    const float* __restrict__ joint, float* __restrict__ out)
{
    gemm_core<EPI_ADD, 0>(ah, cp2, joint, out,
                          blockIdx.y * 64, blockIdx.x * 64,
                          KK, DD, DD, KK / 64, 0, 1.f);
}

// ---------------------------------------------------------------------------
// Single fused prep kernel: flat bf16 converts, no transposes.
// ---------------------------------------------------------------------------
#define N_JOINT (BB * DD)
#define N_CONF  (KK * DD)
#define N_W     (DD * PP)
#define PREP_TOTAL (N_JOINT + N_CONF + 2 * N_W)

__global__ void prep_all(const float* __restrict__ joint,
                         const float* __restrict__ conf,
                         const float* __restrict__ prior,
                         const float* __restrict__ Wq,
                         const float* __restrict__ Wk,
                         bf16* __restrict__ jh, bf16* __restrict__ ch,
                         bf16* __restrict__ cp2,
                         bf16* __restrict__ wqh, bf16* __restrict__ wkh)
{
    int i = (blockIdx.x * blockDim.x + threadIdx.x) * 4;
    if (i < N_JOINT) {
        float4 v = *(const float4*)&joint[i];
        *(__nv_bfloat162*)&jh[i]     = __floats2bfloat162_rn(v.x, v.y);
        *(__nv_bfloat162*)&jh[i + 2] = __floats2bfloat162_rn(v.z, v.w);
    } else if (i < N_JOINT + N_CONF) {
        int idx = i - N_JOINT;
        float4 v = *(const float4*)&conf[idx];
        *(__nv_bfloat162*)&ch[idx]     = __floats2bfloat162_rn(v.x, v.y);
        *(__nv_bfloat162*)&ch[idx + 2] = __floats2bfloat162_rn(v.z, v.w);
        float p = prior[idx >> 10];   // k = idx / DD (4-group never crosses rows)
        *(__nv_bfloat162*)&cp2[idx]     = __floats2bfloat162_rn(v.x * p, v.y * p);
        *(__nv_bfloat162*)&cp2[idx + 2] = __floats2bfloat162_rn(v.z * p, v.w * p);
    } else if (i < N_JOINT + N_CONF + N_W) {
        int idx = i - N_JOINT - N_CONF;
        float4 v = *(const float4*)&Wq[idx];
        *(__nv_bfloat162*)&wqh[idx]     = __floats2bfloat162_rn(v.x, v.y);
        *(__nv_bfloat162*)&wqh[idx + 2] = __floats2bfloat162_rn(v.z, v.w);
    } else {
        int idx = i - N_JOINT - N_CONF - N_W;
        float4 v = *(const float4*)&Wk[idx];
        *(__nv_bfloat162*)&wkh[idx]     = __floats2bfloat162_rn(v.x, v.y);
        *(__nv_bfloat162*)&wkh[idx + 2] = __floats2bfloat162_rn(v.z, v.w);
    }
}

// ---------------------------------------------------------------------------
// Warp-per-row softmax over K=256, summing 4 split-K partials.
// 256 threads = 8 warps = 8 rows per block; grid = BB/8 = 128.
// Lane l owns cols [l*4, l*4+4) and [128+l*4, 128+l*4+4) (two float4 groups).
// No shared memory, no block barriers — pure shfl reductions.
// ---------------------------------------------------------------------------
__global__ __launch_bounds__(256) void softmax_warp(const float* __restrict__ s,
                                                    bf16* __restrict__ a)
{
    const int warp = (blockIdx.x << 3) + (threadIdx.x >> 5);  // row 0..1023
    const int lane = threadIdx.x & 31;
    const size_t rowoff = (size_t)warp * KK;
    const size_t c0 = rowoff + lane * 4;
    const size_t c1 = c0 + 128;
    const size_t PSTRIDE = (size_t)BB * KK;

    // Sum the 4 partials (8 independent float4 loads, fully coalesced)
    float4 v0 = *(const float4*)&s[c0];
    float4 v1 = *(const float4*)&s[c1];
    #pragma unroll
    for (int p = 1; p < 4; p++) {
        float4 u0 = *(const float4*)&s[c0 + p * PSTRIDE];
        float4 u1 = *(const float4*)&s[c1 + p * PSTRIDE];
        v0.x += u0.x; v0.y += u0.y; v0.z += u0.z; v0.w += u0.w;
        v1.x += u1.x; v1.y += u1.y; v1.z += u1.z; v1.w += u1.w;
    }

    // Row max
    float m = fmaxf(fmaxf(fmaxf(v0.x, v0.y), fmaxf(v0.z, v0.w)),
                    fmaxf(fmaxf(v1.x, v1.y), fmaxf(v1.z, v1.w)));
    #pragma unroll
    for (int o = 16; o; o >>= 1) m = fmaxf(m, __shfl_xor_sync(~0u, m, o));

    // Exp
    float e[8];
    e[0] = __expf(v0.x - m); e[1] = __expf(v0.y - m);
    e[2] = __expf(v0.z - m); e[3] = __expf(v0.w - m);
    e[4] = __expf(v1.x - m); e[5] = __expf(v1.y - m);
    e[6] = __expf(v1.z - m); e[7] = __expf(v1.w - m);

    // Row sum
    float sm = ((e[0] + e[1]) + (e[2] + e[3])) + ((e[4] + e[5]) + (e[6] + e[7]));
    #pragma unroll
    for (int o = 16; o; o >>= 1) sm += __shfl_xor_sync(~0u, sm, o);
    const float inv = 1.0f / sm;

    // Write 8 bf16 as two 8-byte packed stores
    __nv_bfloat162 o0 = __floats2bfloat162_rn(e[0] * inv, e[1] * inv);
    __nv_bfloat162 o1 = __floats2bfloat162_rn(e[2] * inv, e[3] * inv);
    __nv_bfloat162 o2 = __floats2bfloat162_rn(e[4] * inv, e[5] * inv);
    __nv_bfloat162 o3 = __floats2bfloat162_rn(e[6] * inv, e[7] * inv);
    uint2 pack0 = make_uint2(*(uint32_t*)&o0, *(uint32_t*)&o1);
    uint2 pack1 = make_uint2(*(uint32_t*)&o2, *(uint32_t*)&o3);
    *(uint2*)&a[c0] = pack0;
    *(uint2*)&a[c1] = pack1;
}

// ---------------------------------------------------------------------------
extern "C" void kernel_launch(void* const* d_in, const int* in_sizes, int n_in,
                              void* d_out, int out_size)
{
    const float* joint = (const float*)d_in[0];   // [1024,1024]
    const float* conf  = (const float*)d_in[1];   // [256,1024]
    const float* prior = (const float*)d_in[2];   // [256,1]
    const float* Wq    = (const float*)d_in[3];   // [1024,768]
    const float* Wk    = (const float*)d_in[4];   // [1024,768]
    float* out = (float*)d_out;                   // [1024,1024]

    bf16 *jh, *ch, *wqh, *wkh, *cp2, *qh, *kh, *ah; float* s;
    cudaGetSymbolAddress((void**)&jh,  g_jh);
    cudaGetSymbolAddress((void**)&ch,  g_ch);
    cudaGetSymbolAddress((void**)&wqh, g_wqh);
    cudaGetSymbolAddress((void**)&wkh, g_wkh);
    cudaGetSymbolAddress((void**)&cp2, g_cp2);
    cudaGetSymbolAddress((void**)&qh,  g_qh);
    cudaGetSymbolAddress((void**)&kh,  g_kh);
    cudaGetSymbolAddress((void**)&s,   g_s);
    cudaGetSymbolAddress((void**)&ah,  g_ah);

    const int SMEM = 2 * STAGE_BYTES;  // 32 KB (<48KB default dyn limit)

    // 1) prep: single fused bf16 convert
    prep_all<<<PREP_TOTAL / 1024, 256>>>(joint, conf, prior, Wq, Wk,
                                         jh, ch, cp2, wqh, wkh);
    // 2) q-proj + k-proj fused: 240 CTAs
    proj_kernel<<<240, 128, SMEM>>>(jh, wqh, ch, wkh, qh, kh);
    // 3) scores split-K x4: 4x16x4 = 256 CTAs, fp32 partials
    scores_kernel<<<dim3(KK / 64, BB / 64, 4), 128, SMEM>>>(qh, kh, s);
    // 4) warp-per-row softmax over summed partials -> bf16 attn
    softmax_warp<<<BB / 8, 256>>>(s, ah);
    // 5) out = attn @ (conf*prior) + joint: 16x16 = 256 CTAs
    out_kernel<<<dim3(DD / 64, BB / 64), 128, SMEM>>>(ah, cp2, joint, out);
}